// round 10
// baseline (speedup 1.0000x reference)
#include <cuda_runtime.h>
#include <cuda_fp16.h>
#include <math.h>

#define N_NODES   100000
#define N_EDGES   1600000
#define N_FEAT    50
#define HIDDEN    16
#define N_CLASSES 10
#define REP       4            // counter replicas per node (shortens RMW chains)
#define SUBCAP    24           // slots per replica; Binom(deg,1/4)~Poisson(4), P(>=24)~8e-12
#define ROWCAP    (REP * SUBCAP)   // 96 ints per node
#define E8        (N_EDGES / 8)

typedef unsigned long long ull;

// ---- packed f32x2 helpers (sm_103a) ----
__device__ __forceinline__ ull pk2(float lo, float hi) {
    ull r;
    asm("mov.b64 %0, {%1, %2};" : "=l"(r) : "f"(lo), "f"(hi));
    return r;
}
__device__ __forceinline__ void upk2(float& lo, float& hi, ull v) {
    asm("mov.b64 {%0, %1}, %2;" : "=f"(lo), "=f"(hi) : "l"(v));
}
__device__ __forceinline__ ull fma2(ull a, ull b, ull c) {
    ull d;
    asm("fma.rn.f32x2 %0, %1, %2, %3;" : "=l"(d) : "l"(a), "l"(b), "l"(c));
    return d;
}

// ---- scratch (static device globals; zero-initialized at load) ----
__device__ __align__(16) int g_cnt4[N_NODES * REP];   // replicated counters
__device__ float g_dinv[N_NODES];
__device__ __align__(16) int g_csrp[N_NODES * ROWCAP]; // sub-bucketed CSR (src ids)
__device__ __align__(16) float  g_xw0[N_NODES * HIDDEN];   // x@w1_0 + b1 (fp32)
__device__ __align__(16) __half g_xp1h[N_NODES * HIDDEN];  // fp16 dinv*(x@w1_1)
__device__ __align__(16) float  g_hw [N_NODES * HIDDEN];   // h@w2_0 + b2 (fp32)
__device__ __align__(16) __half g_hph[N_NODES * HIDDEN];   // fp16 dinv*(h@w2_1)

// ---- K1: single-pass sub-bucket scatter; replica = lane&3 ----
__global__ void k_scatter1(const int* __restrict__ ei) {
    int e8 = blockIdx.x * blockDim.x + threadIdx.x;
    if (e8 >= E8) return;
    int rep = threadIdx.x & 3;
    const int4* sp = (const int4*)ei;
    const int4* dp = (const int4*)(ei + N_EDGES);
    int4 s0 = sp[e8 * 2], s1 = sp[e8 * 2 + 1];
    int4 d0 = dp[e8 * 2], d1 = dp[e8 * 2 + 1];
    int p0 = atomicAdd(&g_cnt4[d0.x * REP + rep], 1);
    int p1 = atomicAdd(&g_cnt4[d0.y * REP + rep], 1);
    int p2 = atomicAdd(&g_cnt4[d0.z * REP + rep], 1);
    int p3 = atomicAdd(&g_cnt4[d0.w * REP + rep], 1);
    int p4 = atomicAdd(&g_cnt4[d1.x * REP + rep], 1);
    int p5 = atomicAdd(&g_cnt4[d1.y * REP + rep], 1);
    int p6 = atomicAdd(&g_cnt4[d1.z * REP + rep], 1);
    int p7 = atomicAdd(&g_cnt4[d1.w * REP + rep], 1);
    int rb = rep * SUBCAP;
    if (p0 < SUBCAP) g_csrp[d0.x * ROWCAP + rb + p0] = s0.x;
    if (p1 < SUBCAP) g_csrp[d0.y * ROWCAP + rb + p1] = s0.y;
    if (p2 < SUBCAP) g_csrp[d0.z * ROWCAP + rb + p2] = s0.z;
    if (p3 < SUBCAP) g_csrp[d0.w * ROWCAP + rb + p3] = s0.w;
    if (p4 < SUBCAP) g_csrp[d1.x * ROWCAP + rb + p4] = s1.x;
    if (p5 < SUBCAP) g_csrp[d1.y * ROWCAP + rb + p5] = s1.y;
    if (p6 < SUBCAP) g_csrp[d1.z * ROWCAP + rb + p6] = s1.z;
    if (p7 < SUBCAP) g_csrp[d1.w * ROWCAP + rb + p7] = s1.w;
}

// ---- K2: layer-1 projections; dinv from summed replica counters ----
__global__ void k_proj1(const float* __restrict__ x,
                        const float* __restrict__ w0,
                        const float* __restrict__ w1,
                        const float* __restrict__ b1) {
    __shared__ ull sw0p[N_FEAT * HIDDEN / 2];
    __shared__ ull sw1p[N_FEAT * HIDDEN / 2];
    __shared__ float sb[HIDDEN];
    for (int i = threadIdx.x; i < N_FEAT * HIDDEN; i += blockDim.x) {
        ((float*)sw0p)[i] = w0[i];
        ((float*)sw1p)[i] = w1[i];
    }
    if (threadIdx.x < HIDDEN) sb[threadIdx.x] = b1[threadIdx.x];
    __syncthreads();

    int n = blockIdx.x * blockDim.x + threadIdx.x;
    if (n >= N_NODES) return;

    int4 lv = *(const int4*)(g_cnt4 + n * REP);
    int d = lv.x + lv.y + lv.z + lv.w;
    float dn = (d > 0) ? rsqrtf((float)d) : 0.0f;
    g_dinv[n] = dn;

    ull a0[8], a1[8];
    ull z = pk2(0.0f, 0.0f);
#pragma unroll
    for (int p = 0; p < 8; p++) { a0[p] = z; a1[p] = z; }

    const float2* xr = (const float2*)(x + (size_t)n * N_FEAT);  // 50 even
#pragma unroll 5
    for (int k2 = 0; k2 < N_FEAT / 2; k2++) {
        float2 xv = __ldg(&xr[k2]);
        ull xa = pk2(xv.x, xv.x);
        ull xb = pk2(xv.y, xv.y);
        const ull* w0a = sw0p + (2 * k2) * 8;
        const ull* w1a = sw1p + (2 * k2) * 8;
#pragma unroll
        for (int p = 0; p < 8; p++) {
            a0[p] = fma2(xa, w0a[p],     a0[p]);
            a0[p] = fma2(xb, w0a[8 + p], a0[p]);
            a1[p] = fma2(xa, w1a[p],     a1[p]);
            a1[p] = fma2(xb, w1a[8 + p], a1[p]);
        }
    }
    float4* o0 = (float4*)(g_xw0 + (size_t)n * HIDDEN);
    __half2 hx[8];
#pragma unroll
    for (int q = 0; q < 4; q++) {
        float v0a, v0b, v0c, v0d, v1a, v1b, v1c, v1d;
        upk2(v0a, v0b, a0[q * 2]);
        upk2(v0c, v0d, a0[q * 2 + 1]);
        upk2(v1a, v1b, a1[q * 2]);
        upk2(v1c, v1d, a1[q * 2 + 1]);
        float4 r0;
        r0.x = v0a + sb[q * 4 + 0];
        r0.y = v0b + sb[q * 4 + 1];
        r0.z = v0c + sb[q * 4 + 2];
        r0.w = v0d + sb[q * 4 + 3];
        o0[q] = r0;
        hx[q * 2 + 0] = __floats2half2_rn(dn * v1a, dn * v1b);
        hx[q * 2 + 1] = __floats2half2_rn(dn * v1c, dn * v1d);
    }
    uint4* oh = (uint4*)(g_xp1h + (size_t)n * HIDDEN);
    oh[0] = *(uint4*)&hx[0];
    oh[1] = *(uint4*)&hx[4];
}

// fp16 gather accumulate: v holds 4 half2 (8 channels)
__device__ __forceinline__ void acc_h8(float2* ac, uint4 v) {
    float2 f;
    f = __half22float2(*(__half2*)&v.x); ac[0].x += f.x; ac[0].y += f.y;
    f = __half22float2(*(__half2*)&v.y); ac[1].x += f.x; ac[1].y += f.y;
    f = __half22float2(*(__half2*)&v.z); ac[2].x += f.x; ac[2].y += f.y;
    f = __half22float2(*(__half2*)&v.w); ac[3].x += f.x; ac[3].y += f.y;
}

// gather over 4 sub-buckets; lens from one int4 load
__device__ __forceinline__ void gather_bucket4(const uint4* __restrict__ pay,
                                               int node, int q, int4 lv,
                                               float2* ac) {
#pragma unroll
    for (int r = 0; r < REP; r++) {
        int len = (r == 0) ? lv.x : (r == 1) ? lv.y : (r == 2) ? lv.z : lv.w;
        len = min(len, SUBCAP);
        const int* base = g_csrp + node * ROWCAP + r * SUBCAP;  // 96B-aligned
        const int4* ip = (const int4*)base;
        int n4 = len >> 2;
        for (int i = 0; i < n4; i++) {
            int4 s = __ldg(&ip[i]);
            uint4 v0 = __ldg(&pay[s.x * 2 + q]);
            uint4 v1 = __ldg(&pay[s.y * 2 + q]);
            uint4 v2 = __ldg(&pay[s.z * 2 + q]);
            uint4 v3 = __ldg(&pay[s.w * 2 + q]);
            acc_h8(ac, v0); acc_h8(ac, v1); acc_h8(ac, v2); acc_h8(ac, v3);
        }
        for (int j = n4 * 4; j < len; j++) {
            int s = __ldg(&base[j]);
            acc_h8(ac, __ldg(&pay[s * 2 + q]));
        }
    }
}

// ---- K3: fused layer-1 agg + relu + layer-2 proj. 2 lanes/node ----
__global__ void k_agg1p2(const float* __restrict__ w0,
                         const float* __restrict__ w1,
                         const float* __restrict__ b2) {
    __shared__ float sw0[HIDDEN][HIDDEN];   // [k][c], cols 10..15 = 0
    __shared__ float sw1[HIDDEN][HIDDEN];
    __shared__ float sb[HIDDEN];
    int t = threadIdx.x;
    {
        int k = t >> 4, c = t & 15;
        sw0[k][c] = (c < N_CLASSES) ? w0[k * N_CLASSES + c] : 0.0f;
        sw1[k][c] = (c < N_CLASSES) ? w1[k * N_CLASSES + c] : 0.0f;
    }
    if (t < HIDDEN) sb[t] = (t < N_CLASSES) ? b2[t] : 0.0f;
    __syncthreads();

    int gid  = blockIdx.x * blockDim.x + t;   // N_NODES*2 threads (guarded)
    int node = gid >> 1;
    int q    = gid & 1;
    if (node >= N_NODES) return;

    int4 lv = *(const int4*)(g_cnt4 + node * REP);
    float2 ac[4] = {{0.f,0.f},{0.f,0.f},{0.f,0.f},{0.f,0.f}};
    gather_bucket4((const uint4*)g_xp1h, node, q, lv, ac);

    float dn = g_dinv[node];
    const float4* xw = (const float4*)g_xw0;
    float4 f0 = xw[node * 4 + q * 2];
    float4 f1 = xw[node * 4 + q * 2 + 1];
    float h[8];
    h[0] = fmaxf(f0.x + dn * ac[0].x, 0.0f);
    h[1] = fmaxf(f0.y + dn * ac[0].y, 0.0f);
    h[2] = fmaxf(f0.z + dn * ac[1].x, 0.0f);
    h[3] = fmaxf(f0.w + dn * ac[1].y, 0.0f);
    h[4] = fmaxf(f1.x + dn * ac[2].x, 0.0f);
    h[5] = fmaxf(f1.y + dn * ac[2].y, 0.0f);
    h[6] = fmaxf(f1.z + dn * ac[3].x, 0.0f);
    h[7] = fmaxf(f1.w + dn * ac[3].y, 0.0f);

    // layer-2 projection: channels q*8..q*8+7 ; h[k] via width-2 shuffle
    float A0[8], A1[8];
    int cb = q * 8;
#pragma unroll
    for (int i = 0; i < 8; i++) { A0[i] = sb[cb + i]; A1[i] = 0.0f; }
#pragma unroll
    for (int k = 0; k < HIDDEN; k++) {
        float hk = __shfl_sync(0xffffffffu, h[k & 7], k >> 3, 2);
#pragma unroll
        for (int i = 0; i < 8; i++) {
            A0[i] = fmaf(hk, sw0[k][cb + i], A0[i]);
            A1[i] = fmaf(hk, sw1[k][cb + i], A1[i]);
        }
    }
    float4* hw = (float4*)g_hw;
    float4 o0, o1;
    o0.x = A0[0]; o0.y = A0[1]; o0.z = A0[2]; o0.w = A0[3];
    o1.x = A0[4]; o1.y = A0[5]; o1.z = A0[6]; o1.w = A0[7];
    hw[node * 4 + q * 2]     = o0;
    hw[node * 4 + q * 2 + 1] = o1;
    __half2 hp[4];
#pragma unroll
    for (int i = 0; i < 4; i++)
        hp[i] = __floats2half2_rn(dn * A1[2 * i], dn * A1[2 * i + 1]);
    ((uint4*)g_hph)[node * 2 + q] = *(uint4*)&hp[0];
}

// ---- K4: layer-2 aggregation + log_softmax; resets counters for replay ----
__global__ void k_agg2(float* __restrict__ out) {
    int gid  = blockIdx.x * blockDim.x + threadIdx.x;
    int node = gid >> 1;
    int q    = gid & 1;
    if (node >= N_NODES) return;

    int4 lv = *(const int4*)(g_cnt4 + node * REP);
    if (q == 0)                                   // replay-idempotent
        *(int4*)(g_cnt4 + node * REP) = make_int4(0, 0, 0, 0);
    float2 ac[4] = {{0.f,0.f},{0.f,0.f},{0.f,0.f},{0.f,0.f}};
    gather_bucket4((const uint4*)g_hph, node, q, lv, ac);

    float dn = g_dinv[node];
    const float4* hwv = (const float4*)g_hw;
    float4 f0 = hwv[node * 4 + q * 2];
    float4 f1 = hwv[node * 4 + q * 2 + 1];
    float L[8];
    L[0] = f0.x + dn * ac[0].x;
    L[1] = f0.y + dn * ac[0].y;
    L[2] = f0.z + dn * ac[1].x;
    L[3] = f0.w + dn * ac[1].y;
    L[4] = f1.x + dn * ac[2].x;
    L[5] = f1.y + dn * ac[2].y;
    L[6] = f1.z + dn * ac[3].x;
    L[7] = f1.w + dn * ac[3].y;

    // valid channels: lane 0 -> c0..7 (all), lane 1 -> c8,c9 (i<2)
    int nvalid = q ? 2 : 8;
    float m = -1e30f;
#pragma unroll
    for (int i = 0; i < 8; i++) if (i < nvalid) m = fmaxf(m, L[i]);
    m = fmaxf(m, __shfl_xor_sync(0xffffffffu, m, 1, 2));
    float s = 0.0f;
#pragma unroll
    for (int i = 0; i < 8; i++) if (i < nvalid) s += expf(L[i] - m);
    s += __shfl_xor_sync(0xffffffffu, s, 1, 2);
    float lse = m + logf(s);

    float* op = out + (size_t)node * N_CLASSES;
    if (q == 0) {
#pragma unroll
        for (int i = 0; i < 4; i++)
            ((float2*)op)[i] = make_float2(L[2 * i] - lse, L[2 * i + 1] - lse);
    } else {
        ((float2*)(op + 8))[0] = make_float2(L[0] - lse, L[1] - lse);
    }
}

extern "C" void kernel_launch(void* const* d_in, const int* in_sizes, int n_in,
                              void* d_out, int out_size) {
    const float* x    = (const float*)d_in[0];
    const int*   ei   = (const int*)d_in[1];     // int32: JAX x64 disabled
    const float* w1_0 = (const float*)d_in[2];
    const float* w1_1 = (const float*)d_in[3];
    const float* b1   = (const float*)d_in[4];
    const float* w2_0 = (const float*)d_in[5];
    const float* w2_1 = (const float*)d_in[6];
    const float* b2   = (const float*)d_in[7];
    float* out = (float*)d_out;

    const int SB = (E8 + 255) / 256;             // 782
    const int PB = (N_NODES + 255) / 256;        // 391
    const int GA = (N_NODES * 2 + 255) / 256;    // 782
    k_scatter1<<<SB, 256>>>(ei);
    k_proj1   <<<PB, 256>>>(x, w1_0, w1_1, b1);
    k_agg1p2  <<<GA, 256>>>(w2_0, w2_1, b2);
    k_agg2    <<<GA, 256>>>(out);
}

// round 11
// speedup vs baseline: 1.3573x; 1.3573x over previous
#include <cuda_runtime.h>
#include <cuda_fp16.h>
#include <math.h>

#define N_NODES   100000
#define N_EDGES   1600000
#define N_FEAT    50
#define HIDDEN    16
#define N_CLASSES 10
#define CAP       64           // bucket capacity; deg ~ Poisson(16), P(>=64)~2e-18
#define E4        (N_EDGES / 4)

typedef unsigned long long ull;

// ---- packed f32x2 helpers (sm_103a) ----
__device__ __forceinline__ ull pk2(float lo, float hi) {
    ull r;
    asm("mov.b64 %0, {%1, %2};" : "=l"(r) : "f"(lo), "f"(hi));
    return r;
}
__device__ __forceinline__ void upk2(float& lo, float& hi, ull v) {
    asm("mov.b64 {%0, %1}, %2;" : "=f"(lo), "=f"(hi) : "l"(v));
}
__device__ __forceinline__ ull fma2(ull a, ull b, ull c) {
    ull d;
    asm("fma.rn.f32x2 %0, %1, %2, %3;" : "=l"(d) : "l"(a), "l"(b), "l"(c));
    return d;
}

// ---- scratch (static device globals; zero-initialized at load) ----
__device__ int   g_cnt[N_NODES];              // bucket fill counts (reset by agg2)
__device__ float g_dinv[N_NODES];
__device__ __align__(16) int g_csrp[N_NODES * CAP];  // padded bucket CSR (src ids)
__device__ __align__(16) float  g_xw0[N_NODES * HIDDEN];   // x@w1_0 + b1 (fp32)
__device__ __align__(16) __half g_xp1h[N_NODES * HIDDEN];  // fp16 dinv*(x@w1_1)
__device__ __align__(16) float  g_hw [N_NODES * HIDDEN];   // h@w2_0 + b2 (fp32)
__device__ __align__(16) __half g_hph[N_NODES * HIDDEN];   // fp16 dinv*(h@w2_1)

// ---- K1: single-pass bucket scatter; 4 edges/thread (grid 1563) ----
__global__ void k_scatter1(const int* __restrict__ ei) {
    int e4 = blockIdx.x * blockDim.x + threadIdx.x;
    if (e4 >= E4) return;
    int4 s = ((const int4*)ei)[e4];
    int4 d = ((const int4*)(ei + N_EDGES))[e4];
    int p0 = atomicAdd(&g_cnt[d.x], 1);
    int p1 = atomicAdd(&g_cnt[d.y], 1);
    int p2 = atomicAdd(&g_cnt[d.z], 1);
    int p3 = atomicAdd(&g_cnt[d.w], 1);
    if (p0 < CAP) g_csrp[d.x * CAP + p0] = s.x;
    if (p1 < CAP) g_csrp[d.y * CAP + p1] = s.y;
    if (p2 < CAP) g_csrp[d.z * CAP + p2] = s.z;
    if (p3 < CAP) g_csrp[d.w * CAP + p3] = s.w;
}

// ---- K2: layer-1 projections; computes dinv from cnt ----
__global__ void k_proj1(const float* __restrict__ x,
                        const float* __restrict__ w0,
                        const float* __restrict__ w1,
                        const float* __restrict__ b1) {
    __shared__ ull sw0p[N_FEAT * HIDDEN / 2];
    __shared__ ull sw1p[N_FEAT * HIDDEN / 2];
    __shared__ float sb[HIDDEN];
    for (int i = threadIdx.x; i < N_FEAT * HIDDEN; i += blockDim.x) {
        ((float*)sw0p)[i] = w0[i];
        ((float*)sw1p)[i] = w1[i];
    }
    if (threadIdx.x < HIDDEN) sb[threadIdx.x] = b1[threadIdx.x];
    __syncthreads();

    int n = blockIdx.x * blockDim.x + threadIdx.x;
    if (n >= N_NODES) return;

    int d = g_cnt[n];
    float dn = (d > 0) ? rsqrtf((float)d) : 0.0f;
    g_dinv[n] = dn;

    ull a0[8], a1[8];
    ull z = pk2(0.0f, 0.0f);
#pragma unroll
    for (int p = 0; p < 8; p++) { a0[p] = z; a1[p] = z; }

    const float2* xr = (const float2*)(x + (size_t)n * N_FEAT);  // 50 even
#pragma unroll 5
    for (int k2 = 0; k2 < N_FEAT / 2; k2++) {
        float2 xv = __ldg(&xr[k2]);
        ull xa = pk2(xv.x, xv.x);
        ull xb = pk2(xv.y, xv.y);
        const ull* w0a = sw0p + (2 * k2) * 8;
        const ull* w1a = sw1p + (2 * k2) * 8;
#pragma unroll
        for (int p = 0; p < 8; p++) {
            a0[p] = fma2(xa, w0a[p],     a0[p]);
            a0[p] = fma2(xb, w0a[8 + p], a0[p]);
            a1[p] = fma2(xa, w1a[p],     a1[p]);
            a1[p] = fma2(xb, w1a[8 + p], a1[p]);
        }
    }
    float4* o0 = (float4*)(g_xw0 + (size_t)n * HIDDEN);
    __half2 hx[8];
#pragma unroll
    for (int q = 0; q < 4; q++) {
        float v0a, v0b, v0c, v0d, v1a, v1b, v1c, v1d;
        upk2(v0a, v0b, a0[q * 2]);
        upk2(v0c, v0d, a0[q * 2 + 1]);
        upk2(v1a, v1b, a1[q * 2]);
        upk2(v1c, v1d, a1[q * 2 + 1]);
        float4 r0;
        r0.x = v0a + sb[q * 4 + 0];
        r0.y = v0b + sb[q * 4 + 1];
        r0.z = v0c + sb[q * 4 + 2];
        r0.w = v0d + sb[q * 4 + 3];
        o0[q] = r0;
        hx[q * 2 + 0] = __floats2half2_rn(dn * v1a, dn * v1b);
        hx[q * 2 + 1] = __floats2half2_rn(dn * v1c, dn * v1d);
    }
    uint4* oh = (uint4*)(g_xp1h + (size_t)n * HIDDEN);
    oh[0] = *(uint4*)&hx[0];
    oh[1] = *(uint4*)&hx[4];
}

// fp16 gather accumulate: v holds 4 half2 (8 channels)
__device__ __forceinline__ void acc_h8(float2* ac, uint4 v) {
    float2 f;
    f = __half22float2(*(__half2*)&v.x); ac[0].x += f.x; ac[0].y += f.y;
    f = __half22float2(*(__half2*)&v.y); ac[1].x += f.x; ac[1].y += f.y;
    f = __half22float2(*(__half2*)&v.z); ac[2].x += f.x; ac[2].y += f.y;
    f = __half22float2(*(__half2*)&v.w); ac[3].x += f.x; ac[3].y += f.y;
}

// shared gather loop: int4 idx loads over this node's bucket
__device__ __forceinline__ void gather_bucket(const uint4* __restrict__ pay,
                                              int node, int q, int len,
                                              float2* ac) {
    const int4* ip = (const int4*)(g_csrp + node * CAP);   // 16B-aligned
    int n4 = len >> 2;
#pragma unroll 2
    for (int i = 0; i < n4; i++) {
        int4 s = __ldg(&ip[i]);
        uint4 v0 = __ldg(&pay[s.x * 2 + q]);
        uint4 v1 = __ldg(&pay[s.y * 2 + q]);
        uint4 v2 = __ldg(&pay[s.z * 2 + q]);
        uint4 v3 = __ldg(&pay[s.w * 2 + q]);
        acc_h8(ac, v0); acc_h8(ac, v1); acc_h8(ac, v2); acc_h8(ac, v3);
    }
    for (int j = n4 * 4; j < len; j++) {
        int s = __ldg(&g_csrp[node * CAP + j]);
        acc_h8(ac, __ldg(&pay[s * 2 + q]));
    }
}

// ---- K3: fused layer-1 agg + relu + layer-2 proj. 2 lanes/node, 128-thr blocks ----
__global__ void __launch_bounds__(128)
k_agg1p2(const float* __restrict__ w0,
         const float* __restrict__ w1,
         const float* __restrict__ b2) {
    __shared__ float sw0[HIDDEN][HIDDEN];   // [k][c], cols 10..15 = 0
    __shared__ float sw1[HIDDEN][HIDDEN];
    __shared__ float sb[HIDDEN];
    int t = threadIdx.x;
    for (int i = t; i < HIDDEN * HIDDEN; i += blockDim.x) {
        int k = i >> 4, c = i & 15;
        sw0[k][c] = (c < N_CLASSES) ? w0[k * N_CLASSES + c] : 0.0f;
        sw1[k][c] = (c < N_CLASSES) ? w1[k * N_CLASSES + c] : 0.0f;
    }
    if (t < HIDDEN) sb[t] = (t < N_CLASSES) ? b2[t] : 0.0f;
    __syncthreads();

    int gid  = blockIdx.x * blockDim.x + t;   // N_NODES*2 threads (guarded)
    int node = gid >> 1;
    int q    = gid & 1;
    if (node >= N_NODES) return;

    int len = g_cnt[node];
    float2 ac[4] = {{0.f,0.f},{0.f,0.f},{0.f,0.f},{0.f,0.f}};
    gather_bucket((const uint4*)g_xp1h, node, q, len, ac);

    float dn = g_dinv[node];
    const float4* xw = (const float4*)g_xw0;
    float4 f0 = xw[node * 4 + q * 2];
    float4 f1 = xw[node * 4 + q * 2 + 1];
    float h[8];
    h[0] = fmaxf(f0.x + dn * ac[0].x, 0.0f);
    h[1] = fmaxf(f0.y + dn * ac[0].y, 0.0f);
    h[2] = fmaxf(f0.z + dn * ac[1].x, 0.0f);
    h[3] = fmaxf(f0.w + dn * ac[1].y, 0.0f);
    h[4] = fmaxf(f1.x + dn * ac[2].x, 0.0f);
    h[5] = fmaxf(f1.y + dn * ac[2].y, 0.0f);
    h[6] = fmaxf(f1.z + dn * ac[3].x, 0.0f);
    h[7] = fmaxf(f1.w + dn * ac[3].y, 0.0f);

    // layer-2 projection: channels q*8..q*8+7 ; h[k] via width-2 shuffle
    float A0[8], A1[8];
    int cb = q * 8;
#pragma unroll
    for (int i = 0; i < 8; i++) { A0[i] = sb[cb + i]; A1[i] = 0.0f; }
#pragma unroll
    for (int k = 0; k < HIDDEN; k++) {
        float hk = __shfl_sync(0xffffffffu, h[k & 7], k >> 3, 2);
#pragma unroll
        for (int i = 0; i < 8; i++) {
            A0[i] = fmaf(hk, sw0[k][cb + i], A0[i]);
            A1[i] = fmaf(hk, sw1[k][cb + i], A1[i]);
        }
    }
    float4* hw = (float4*)g_hw;
    float4 o0, o1;
    o0.x = A0[0]; o0.y = A0[1]; o0.z = A0[2]; o0.w = A0[3];
    o1.x = A0[4]; o1.y = A0[5]; o1.z = A0[6]; o1.w = A0[7];
    hw[node * 4 + q * 2]     = o0;
    hw[node * 4 + q * 2 + 1] = o1;
    __half2 hp[4];
#pragma unroll
    for (int i = 0; i < 4; i++)
        hp[i] = __floats2half2_rn(dn * A1[2 * i], dn * A1[2 * i + 1]);
    ((uint4*)g_hph)[node * 2 + q] = *(uint4*)&hp[0];
}

// ---- K4: layer-2 aggregation + log_softmax; resets cnt for next replay ----
__global__ void __launch_bounds__(128)
k_agg2(float* __restrict__ out) {
    int gid  = blockIdx.x * blockDim.x + threadIdx.x;
    int node = gid >> 1;
    int q    = gid & 1;
    if (node >= N_NODES) return;

    int len = g_cnt[node];
    if (q == 0) g_cnt[node] = 0;          // replay-idempotent
    float2 ac[4] = {{0.f,0.f},{0.f,0.f},{0.f,0.f},{0.f,0.f}};
    gather_bucket((const uint4*)g_hph, node, q, len, ac);

    float dn = g_dinv[node];
    const float4* hwv = (const float4*)g_hw;
    float4 f0 = hwv[node * 4 + q * 2];
    float4 f1 = hwv[node * 4 + q * 2 + 1];
    float L[8];
    L[0] = f0.x + dn * ac[0].x;
    L[1] = f0.y + dn * ac[0].y;
    L[2] = f0.z + dn * ac[1].x;
    L[3] = f0.w + dn * ac[1].y;
    L[4] = f1.x + dn * ac[2].x;
    L[5] = f1.y + dn * ac[2].y;
    L[6] = f1.z + dn * ac[3].x;
    L[7] = f1.w + dn * ac[3].y;

    // valid channels: lane 0 -> c0..7 (all), lane 1 -> c8,c9 (i<2)
    int nvalid = q ? 2 : 8;
    float m = -1e30f;
#pragma unroll
    for (int i = 0; i < 8; i++) if (i < nvalid) m = fmaxf(m, L[i]);
    m = fmaxf(m, __shfl_xor_sync(0xffffffffu, m, 1, 2));
    float s = 0.0f;
#pragma unroll
    for (int i = 0; i < 8; i++) if (i < nvalid) s += expf(L[i] - m);
    s += __shfl_xor_sync(0xffffffffu, s, 1, 2);
    float lse = m + logf(s);

    float* op = out + (size_t)node * N_CLASSES;
    if (q == 0) {
#pragma unroll
        for (int i = 0; i < 4; i++)
            ((float2*)op)[i] = make_float2(L[2 * i] - lse, L[2 * i + 1] - lse);
    } else {
        ((float2*)(op + 8))[0] = make_float2(L[0] - lse, L[1] - lse);
    }
}

extern "C" void kernel_launch(void* const* d_in, const int* in_sizes, int n_in,
                              void* d_out, int out_size) {
    const float* x    = (const float*)d_in[0];
    const int*   ei   = (const int*)d_in[1];     // int32: JAX x64 disabled
    const float* w1_0 = (const float*)d_in[2];
    const float* w1_1 = (const float*)d_in[3];
    const float* b1   = (const float*)d_in[4];
    const float* w2_0 = (const float*)d_in[5];
    const float* w2_1 = (const float*)d_in[6];
    const float* b2   = (const float*)d_in[7];
    float* out = (float*)d_out;

    const int SB = (E4 + 255) / 256;               // 1563
    const int PB = (N_NODES + 255) / 256;          // 391
    const int GA = (N_NODES * 2 + 127) / 128;      // 1563
    k_scatter1<<<SB, 256>>>(ei);
    k_proj1   <<<PB, 256>>>(x, w1_0, w1_1, b1);
    k_agg1p2  <<<GA, 128>>>(w2_0, w2_1, b2);
    k_agg2    <<<GA, 128>>>(out);
}

// round 12
// speedup vs baseline: 1.3634x; 1.0044x over previous
#include <cuda_runtime.h>
#include <cuda_fp16.h>
#include <math.h>

#define N_NODES   100000
#define N_EDGES   1600000
#define N_FEAT    50
#define HIDDEN    16
#define N_CLASSES 10
#define CAP       64           // bucket capacity; deg ~ Poisson(16), P(>=64)~2e-18
#define E4        (N_EDGES / 4)

typedef unsigned long long ull;

// ---- packed f32x2 helpers (sm_103a) ----
__device__ __forceinline__ ull pk2(float lo, float hi) {
    ull r;
    asm("mov.b64 %0, {%1, %2};" : "=l"(r) : "f"(lo), "f"(hi));
    return r;
}
__device__ __forceinline__ void upk2(float& lo, float& hi, ull v) {
    asm("mov.b64 {%0, %1}, %2;" : "=f"(lo), "=f"(hi) : "l"(v));
}
__device__ __forceinline__ ull fma2(ull a, ull b, ull c) {
    ull d;
    asm("fma.rn.f32x2 %0, %1, %2, %3;" : "=l"(d) : "l"(a), "l"(b), "l"(c));
    return d;
}

// ---- scratch (static device globals; zero-initialized at load) ----
// payload arrays have ONE extra row (index N_NODES) that is never written:
// it stays zero and absorbs gathers for out-of-range bucket slots.
__device__ int   g_cnt[N_NODES];              // bucket fill counts (reset by agg2)
__device__ float g_dinv[N_NODES];
__device__ __align__(16) int g_csrp[N_NODES * CAP];  // padded bucket CSR (src ids)
__device__ __align__(16) float  g_xw0[N_NODES * HIDDEN];         // x@w1_0 + b1
__device__ __align__(16) __half g_xp1h[(N_NODES + 1) * HIDDEN];  // fp16 dinv*(x@w1_1)
__device__ __align__(16) float  g_hw [N_NODES * HIDDEN];         // h@w2_0 + b2
__device__ __align__(16) __half g_hph[(N_NODES + 1) * HIDDEN];   // fp16 dinv*(h@w2_1)

// ---- K1: single-pass bucket scatter; 4 edges/thread ----
__global__ void k_scatter1(const int* __restrict__ ei) {
    int e4 = blockIdx.x * blockDim.x + threadIdx.x;
    if (e4 >= E4) return;
    int4 s = ((const int4*)ei)[e4];
    int4 d = ((const int4*)(ei + N_EDGES))[e4];
    int p0 = atomicAdd(&g_cnt[d.x], 1);
    int p1 = atomicAdd(&g_cnt[d.y], 1);
    int p2 = atomicAdd(&g_cnt[d.z], 1);
    int p3 = atomicAdd(&g_cnt[d.w], 1);
    if (p0 < CAP) g_csrp[d.x * CAP + p0] = s.x;
    if (p1 < CAP) g_csrp[d.y * CAP + p1] = s.y;
    if (p2 < CAP) g_csrp[d.z * CAP + p2] = s.z;
    if (p3 < CAP) g_csrp[d.w * CAP + p3] = s.w;
}

// ---- K2: layer-1 projections; computes dinv from cnt ----
__global__ void k_proj1(const float* __restrict__ x,
                        const float* __restrict__ w0,
                        const float* __restrict__ w1,
                        const float* __restrict__ b1) {
    __shared__ ull sw0p[N_FEAT * HIDDEN / 2];
    __shared__ ull sw1p[N_FEAT * HIDDEN / 2];
    __shared__ float sb[HIDDEN];
    for (int i = threadIdx.x; i < N_FEAT * HIDDEN; i += blockDim.x) {
        ((float*)sw0p)[i] = w0[i];
        ((float*)sw1p)[i] = w1[i];
    }
    if (threadIdx.x < HIDDEN) sb[threadIdx.x] = b1[threadIdx.x];
    __syncthreads();

    int n = blockIdx.x * blockDim.x + threadIdx.x;
    if (n >= N_NODES) return;

    int d = g_cnt[n];
    float dn = (d > 0) ? rsqrtf((float)d) : 0.0f;
    g_dinv[n] = dn;

    ull a0[8], a1[8];
    ull z = pk2(0.0f, 0.0f);
#pragma unroll
    for (int p = 0; p < 8; p++) { a0[p] = z; a1[p] = z; }

    const float2* xr = (const float2*)(x + (size_t)n * N_FEAT);  // 50 even
#pragma unroll 5
    for (int k2 = 0; k2 < N_FEAT / 2; k2++) {
        float2 xv = __ldg(&xr[k2]);
        ull xa = pk2(xv.x, xv.x);
        ull xb = pk2(xv.y, xv.y);
        const ull* w0a = sw0p + (2 * k2) * 8;
        const ull* w1a = sw1p + (2 * k2) * 8;
#pragma unroll
        for (int p = 0; p < 8; p++) {
            a0[p] = fma2(xa, w0a[p],     a0[p]);
            a0[p] = fma2(xb, w0a[8 + p], a0[p]);
            a1[p] = fma2(xa, w1a[p],     a1[p]);
            a1[p] = fma2(xb, w1a[8 + p], a1[p]);
        }
    }
    float4* o0 = (float4*)(g_xw0 + (size_t)n * HIDDEN);
    __half2 hx[8];
#pragma unroll
    for (int q = 0; q < 4; q++) {
        float v0a, v0b, v0c, v0d, v1a, v1b, v1c, v1d;
        upk2(v0a, v0b, a0[q * 2]);
        upk2(v0c, v0d, a0[q * 2 + 1]);
        upk2(v1a, v1b, a1[q * 2]);
        upk2(v1c, v1d, a1[q * 2 + 1]);
        float4 r0;
        r0.x = v0a + sb[q * 4 + 0];
        r0.y = v0b + sb[q * 4 + 1];
        r0.z = v0c + sb[q * 4 + 2];
        r0.w = v0d + sb[q * 4 + 3];
        o0[q] = r0;
        hx[q * 2 + 0] = __floats2half2_rn(dn * v1a, dn * v1b);
        hx[q * 2 + 1] = __floats2half2_rn(dn * v1c, dn * v1d);
    }
    uint4* oh = (uint4*)(g_xp1h + (size_t)n * HIDDEN);
    oh[0] = *(uint4*)&hx[0];
    oh[1] = *(uint4*)&hx[4];
}

// fp16 gather accumulate: v holds 4 half2 (8 channels)
__device__ __forceinline__ void acc_h8(float2* ac, uint4 v) {
    float2 f;
    f = __half22float2(*(__half2*)&v.x); ac[0].x += f.x; ac[0].y += f.y;
    f = __half22float2(*(__half2*)&v.y); ac[1].x += f.x; ac[1].y += f.y;
    f = __half22float2(*(__half2*)&v.z); ac[2].x += f.x; ac[2].y += f.y;
    f = __half22float2(*(__half2*)&v.w); ac[3].x += f.x; ac[3].y += f.y;
}

// branch-free 16-edge gather chunk: unconditional idx loads (bucket storage
// is always CAP ints), out-of-range slots redirected to the zero row.
__device__ __forceinline__ void gather16(const uint4* __restrict__ pay,
                                         const int* __restrict__ base,
                                         int j0, int len, int q, float2* ac) {
    const int4* ip = (const int4*)(base + j0);
    int4 ia = __ldg(&ip[0]);
    int4 ib = __ldg(&ip[1]);
    int4 ic = __ldg(&ip[2]);
    int4 id = __ldg(&ip[3]);
    int s[16];
    s[0]  = ia.x; s[1]  = ia.y; s[2]  = ia.z; s[3]  = ia.w;
    s[4]  = ib.x; s[5]  = ib.y; s[6]  = ib.z; s[7]  = ib.w;
    s[8]  = ic.x; s[9]  = ic.y; s[10] = ic.z; s[11] = ic.w;
    s[12] = id.x; s[13] = id.y; s[14] = id.z; s[15] = id.w;
    uint4 v[16];
#pragma unroll
    for (int k = 0; k < 16; k++) {
        int idx = (j0 + k < len) ? s[k] : N_NODES;   // zero row if past end
        v[k] = __ldg(&pay[idx * 2 + q]);
    }
#pragma unroll
    for (int k = 0; k < 16; k++) acc_h8(ac, v[k]);
}

__device__ __forceinline__ void gather_all(const uint4* __restrict__ pay,
                                           int node, int q, int len,
                                           float2* ac) {
    const int* base = g_csrp + node * CAP;
    gather16(pay, base, 0, len, q, ac);
    if (len > 16) {
        gather16(pay, base, 16, len, q, ac);
        if (len > 32) {
            gather16(pay, base, 32, len, q, ac);
            if (len > 48) gather16(pay, base, 48, len, q, ac);
        }
    }
}

// ---- K3: fused layer-1 agg + relu + layer-2 proj. 2 lanes/node ----
__global__ void __launch_bounds__(128, 6)
k_agg1p2(const float* __restrict__ w0,
         const float* __restrict__ w1,
         const float* __restrict__ b2) {
    __shared__ float sw0[HIDDEN][HIDDEN];   // [k][c], cols 10..15 = 0
    __shared__ float sw1[HIDDEN][HIDDEN];
    __shared__ float sb[HIDDEN];
    int t = threadIdx.x;
    for (int i = t; i < HIDDEN * HIDDEN; i += blockDim.x) {
        int k = i >> 4, c = i & 15;
        sw0[k][c] = (c < N_CLASSES) ? w0[k * N_CLASSES + c] : 0.0f;
        sw1[k][c] = (c < N_CLASSES) ? w1[k * N_CLASSES + c] : 0.0f;
    }
    if (t < HIDDEN) sb[t] = (t < N_CLASSES) ? b2[t] : 0.0f;
    __syncthreads();

    int gid  = blockIdx.x * blockDim.x + t;   // N_NODES*2 threads (guarded)
    int node = gid >> 1;
    int q    = gid & 1;
    if (node >= N_NODES) return;

    int len = g_cnt[node];
    float2 ac[4] = {{0.f,0.f},{0.f,0.f},{0.f,0.f},{0.f,0.f}};
    gather_all((const uint4*)g_xp1h, node, q, len, ac);

    float dn = g_dinv[node];
    const float4* xw = (const float4*)g_xw0;
    float4 f0 = xw[node * 4 + q * 2];
    float4 f1 = xw[node * 4 + q * 2 + 1];
    float h[8];
    h[0] = fmaxf(f0.x + dn * ac[0].x, 0.0f);
    h[1] = fmaxf(f0.y + dn * ac[0].y, 0.0f);
    h[2] = fmaxf(f0.z + dn * ac[1].x, 0.0f);
    h[3] = fmaxf(f0.w + dn * ac[1].y, 0.0f);
    h[4] = fmaxf(f1.x + dn * ac[2].x, 0.0f);
    h[5] = fmaxf(f1.y + dn * ac[2].y, 0.0f);
    h[6] = fmaxf(f1.z + dn * ac[3].x, 0.0f);
    h[7] = fmaxf(f1.w + dn * ac[3].y, 0.0f);

    // layer-2 projection: channels q*8..q*8+7 ; h[k] via width-2 shuffle
    float A0[8], A1[8];
    int cb = q * 8;
#pragma unroll
    for (int i = 0; i < 8; i++) { A0[i] = sb[cb + i]; A1[i] = 0.0f; }
#pragma unroll
    for (int k = 0; k < HIDDEN; k++) {
        float hk = __shfl_sync(0xffffffffu, h[k & 7], k >> 3, 2);
#pragma unroll
        for (int i = 0; i < 8; i++) {
            A0[i] = fmaf(hk, sw0[k][cb + i], A0[i]);
            A1[i] = fmaf(hk, sw1[k][cb + i], A1[i]);
        }
    }
    float4* hw = (float4*)g_hw;
    float4 o0, o1;
    o0.x = A0[0]; o0.y = A0[1]; o0.z = A0[2]; o0.w = A0[3];
    o1.x = A0[4]; o1.y = A0[5]; o1.z = A0[6]; o1.w = A0[7];
    hw[node * 4 + q * 2]     = o0;
    hw[node * 4 + q * 2 + 1] = o1;
    __half2 hp[4];
#pragma unroll
    for (int i = 0; i < 4; i++)
        hp[i] = __floats2half2_rn(dn * A1[2 * i], dn * A1[2 * i + 1]);
    ((uint4*)g_hph)[node * 2 + q] = *(uint4*)&hp[0];
}

// ---- K4: layer-2 aggregation + log_softmax; resets cnt for next replay ----
__global__ void __launch_bounds__(128, 6)
k_agg2(float* __restrict__ out) {
    int gid  = blockIdx.x * blockDim.x + threadIdx.x;
    int node = gid >> 1;
    int q    = gid & 1;
    if (node >= N_NODES) return;

    int len = g_cnt[node];
    if (q == 0) g_cnt[node] = 0;          // replay-idempotent
    float2 ac[4] = {{0.f,0.f},{0.f,0.f},{0.f,0.f},{0.f,0.f}};
    gather_all((const uint4*)g_hph, node, q, len, ac);

    float dn = g_dinv[node];
    const float4* hwv = (const float4*)g_hw;
    float4 f0 = hwv[node * 4 + q * 2];
    float4 f1 = hwv[node * 4 + q * 2 + 1];
    float L[8];
    L[0] = f0.x + dn * ac[0].x;
    L[1] = f0.y + dn * ac[0].y;
    L[2] = f0.z + dn * ac[1].x;
    L[3] = f0.w + dn * ac[1].y;
    L[4] = f1.x + dn * ac[2].x;
    L[5] = f1.y + dn * ac[2].y;
    L[6] = f1.z + dn * ac[3].x;
    L[7] = f1.w + dn * ac[3].y;

    // valid channels: lane 0 -> c0..7 (all), lane 1 -> c8,c9 (i<2)
    int nvalid = q ? 2 : 8;
    float m = -1e30f;
#pragma unroll
    for (int i = 0; i < 8; i++) if (i < nvalid) m = fmaxf(m, L[i]);
    m = fmaxf(m, __shfl_xor_sync(0xffffffffu, m, 1, 2));
    float s = 0.0f;
#pragma unroll
    for (int i = 0; i < 8; i++) if (i < nvalid) s += expf(L[i] - m);
    s += __shfl_xor_sync(0xffffffffu, s, 1, 2);
    float lse = m + logf(s);

    float* op = out + (size_t)node * N_CLASSES;
    if (q == 0) {
#pragma unroll
        for (int i = 0; i < 4; i++)
            ((float2*)op)[i] = make_float2(L[2 * i] - lse, L[2 * i + 1] - lse);
    } else {
        ((float2*)(op + 8))[0] = make_float2(L[0] - lse, L[1] - lse);
    }
}

extern "C" void kernel_launch(void* const* d_in, const int* in_sizes, int n_in,
                              void* d_out, int out_size) {
    const float* x    = (const float*)d_in[0];
    const int*   ei   = (const int*)d_in[1];     // int32: JAX x64 disabled
    const float* w1_0 = (const float*)d_in[2];
    const float* w1_1 = (const float*)d_in[3];
    const float* b1   = (const float*)d_in[4];
    const float* w2_0 = (const float*)d_in[5];
    const float* w2_1 = (const float*)d_in[6];
    const float* b2   = (const float*)d_in[7];
    float* out = (float*)d_out;

    const int SB = (E4 + 255) / 256;               // 1563
    const int PB = (N_NODES + 255) / 256;          // 391
    const int GA = (N_NODES * 2 + 127) / 128;      // 1563
    k_scatter1<<<SB, 256>>>(ei);
    k_proj1   <<<PB, 256>>>(x, w1_0, w1_1, b1);
    k_agg1p2  <<<GA, 128>>>(w2_0, w2_1, b2);
    k_agg2    <<<GA, 128>>>(out);
}

// round 13
// speedup vs baseline: 1.4774x; 1.0837x over previous
#include <cuda_runtime.h>
#include <cuda_fp16.h>
#include <math.h>

#define N_NODES   100000
#define N_EDGES   1600000
#define N_FEAT    50
#define HIDDEN    16
#define N_CLASSES 10
#define CAP       64           // bucket capacity; deg ~ Poisson(16), P(>=64)~2e-18
#define E4        (N_EDGES / 4)

typedef unsigned long long ull;

// ---- packed f32x2 helpers (sm_103a) ----
__device__ __forceinline__ ull pk2(float lo, float hi) {
    ull r;
    asm("mov.b64 %0, {%1, %2};" : "=l"(r) : "f"(lo), "f"(hi));
    return r;
}
__device__ __forceinline__ void upk2(float& lo, float& hi, ull v) {
    asm("mov.b64 {%0, %1}, %2;" : "=f"(lo), "=f"(hi) : "l"(v));
}
__device__ __forceinline__ ull fma2(ull a, ull b, ull c) {
    ull d;
    asm("fma.rn.f32x2 %0, %1, %2, %3;" : "=l"(d) : "l"(a), "l"(b), "l"(c));
    return d;
}

// ---- scratch (static device globals; zero-initialized at load) ----
// payload arrays have ONE extra row (index N_NODES) that is never written:
// it stays zero and absorbs gathers for out-of-range bucket slots.
__device__ int   g_cnt[N_NODES];              // bucket fill counts (reset by agg2)
__device__ float g_dinv[N_NODES];
__device__ __align__(16) int g_csrp[N_NODES * CAP];  // padded bucket CSR (src ids)
__device__ __align__(16) float  g_xw0[N_NODES * HIDDEN];         // x@w1_0 + b1
__device__ __align__(16) __half g_xp1h[(N_NODES + 1) * HIDDEN];  // fp16 dinv*(x@w1_1)
__device__ __align__(16) float  g_hw [N_NODES * HIDDEN];         // h@w2_0 + b2
__device__ __align__(16) __half g_hph[(N_NODES + 1) * HIDDEN];   // fp16 dinv*(h@w2_1)

// ---- K1: single-pass bucket scatter; 4 edges/thread (stream 0) ----
__global__ void k_scatter1(const int* __restrict__ ei) {
    int e4 = blockIdx.x * blockDim.x + threadIdx.x;
    if (e4 >= E4) return;
    int4 s = ((const int4*)ei)[e4];
    int4 d = ((const int4*)(ei + N_EDGES))[e4];
    int p0 = atomicAdd(&g_cnt[d.x], 1);
    int p1 = atomicAdd(&g_cnt[d.y], 1);
    int p2 = atomicAdd(&g_cnt[d.z], 1);
    int p3 = atomicAdd(&g_cnt[d.w], 1);
    if (p0 < CAP) g_csrp[d.x * CAP + p0] = s.x;
    if (p1 < CAP) g_csrp[d.y * CAP + p1] = s.y;
    if (p2 < CAP) g_csrp[d.z * CAP + p2] = s.z;
    if (p3 < CAP) g_csrp[d.w * CAP + p3] = s.w;
}

// ---- K2: layer-1 projections, UNSCALED (no g_cnt dependency; runs || scatter) ----
// xw0 = x@w1_0 + b1 (fp32) ; xp1h = fp16( x@w1_1 )  [dinv applied by k_scale]
__global__ void k_projU(const float* __restrict__ x,
                        const float* __restrict__ w0,
                        const float* __restrict__ w1,
                        const float* __restrict__ b1) {
    __shared__ ull sw0p[N_FEAT * HIDDEN / 2];
    __shared__ ull sw1p[N_FEAT * HIDDEN / 2];
    __shared__ float sb[HIDDEN];
    for (int i = threadIdx.x; i < N_FEAT * HIDDEN; i += blockDim.x) {
        ((float*)sw0p)[i] = w0[i];
        ((float*)sw1p)[i] = w1[i];
    }
    if (threadIdx.x < HIDDEN) sb[threadIdx.x] = b1[threadIdx.x];
    __syncthreads();

    int n = blockIdx.x * blockDim.x + threadIdx.x;
    if (n >= N_NODES) return;

    ull a0[8], a1[8];
    ull z = pk2(0.0f, 0.0f);
#pragma unroll
    for (int p = 0; p < 8; p++) { a0[p] = z; a1[p] = z; }

    const float2* xr = (const float2*)(x + (size_t)n * N_FEAT);  // 50 even
#pragma unroll 5
    for (int k2 = 0; k2 < N_FEAT / 2; k2++) {
        float2 xv = __ldg(&xr[k2]);
        ull xa = pk2(xv.x, xv.x);
        ull xb = pk2(xv.y, xv.y);
        const ull* w0a = sw0p + (2 * k2) * 8;
        const ull* w1a = sw1p + (2 * k2) * 8;
#pragma unroll
        for (int p = 0; p < 8; p++) {
            a0[p] = fma2(xa, w0a[p],     a0[p]);
            a0[p] = fma2(xb, w0a[8 + p], a0[p]);
            a1[p] = fma2(xa, w1a[p],     a1[p]);
            a1[p] = fma2(xb, w1a[8 + p], a1[p]);
        }
    }
    float4* o0 = (float4*)(g_xw0 + (size_t)n * HIDDEN);
    __half2 hx[8];
#pragma unroll
    for (int q = 0; q < 4; q++) {
        float v0a, v0b, v0c, v0d, v1a, v1b, v1c, v1d;
        upk2(v0a, v0b, a0[q * 2]);
        upk2(v0c, v0d, a0[q * 2 + 1]);
        upk2(v1a, v1b, a1[q * 2]);
        upk2(v1c, v1d, a1[q * 2 + 1]);
        float4 r0;
        r0.x = v0a + sb[q * 4 + 0];
        r0.y = v0b + sb[q * 4 + 1];
        r0.z = v0c + sb[q * 4 + 2];
        r0.w = v0d + sb[q * 4 + 3];
        o0[q] = r0;
        hx[q * 2 + 0] = __floats2half2_rn(v1a, v1b);
        hx[q * 2 + 1] = __floats2half2_rn(v1c, v1d);
    }
    uint4* oh = (uint4*)(g_xp1h + (size_t)n * HIDDEN);
    oh[0] = *(uint4*)&hx[0];
    oh[1] = *(uint4*)&hx[4];
}

// ---- K3: dinv from final cnt; scale xp1h in place (after join) ----
__global__ void k_scale() {
    int n = blockIdx.x * blockDim.x + threadIdx.x;
    if (n >= N_NODES) return;
    int d = g_cnt[n];
    float dn = (d > 0) ? rsqrtf((float)d) : 0.0f;
    g_dinv[n] = dn;
    uint4* p = (uint4*)(g_xp1h + (size_t)n * HIDDEN);
    uint4 v0 = p[0], v1 = p[1];
    __half2* h0 = (__half2*)&v0;
    __half2* h1 = (__half2*)&v1;
#pragma unroll
    for (int i = 0; i < 4; i++) {
        float2 f = __half22float2(h0[i]);
        h0[i] = __floats2half2_rn(dn * f.x, dn * f.y);
        f = __half22float2(h1[i]);
        h1[i] = __floats2half2_rn(dn * f.x, dn * f.y);
    }
    p[0] = v0;
    p[1] = v1;
}

// fp16 gather accumulate: v holds 4 half2 (8 channels)
__device__ __forceinline__ void acc_h8(float2* ac, uint4 v) {
    float2 f;
    f = __half22float2(*(__half2*)&v.x); ac[0].x += f.x; ac[0].y += f.y;
    f = __half22float2(*(__half2*)&v.y); ac[1].x += f.x; ac[1].y += f.y;
    f = __half22float2(*(__half2*)&v.z); ac[2].x += f.x; ac[2].y += f.y;
    f = __half22float2(*(__half2*)&v.w); ac[3].x += f.x; ac[3].y += f.y;
}

// branch-free 16-edge gather chunk (bucket storage is always CAP ints;
// out-of-range slots redirected to the zero row N_NODES).
__device__ __forceinline__ void gather16(const uint4* __restrict__ pay,
                                         const int* __restrict__ base,
                                         int j0, int len, int q, float2* ac) {
    const int4* ip = (const int4*)(base + j0);
    int4 ia = __ldg(&ip[0]);
    int4 ib = __ldg(&ip[1]);
    int4 ic = __ldg(&ip[2]);
    int4 id = __ldg(&ip[3]);
    int s[16];
    s[0]  = ia.x; s[1]  = ia.y; s[2]  = ia.z; s[3]  = ia.w;
    s[4]  = ib.x; s[5]  = ib.y; s[6]  = ib.z; s[7]  = ib.w;
    s[8]  = ic.x; s[9]  = ic.y; s[10] = ic.z; s[11] = ic.w;
    s[12] = id.x; s[13] = id.y; s[14] = id.z; s[15] = id.w;
    uint4 v[16];
#pragma unroll
    for (int k = 0; k < 16; k++) {
        int idx = (j0 + k < len) ? s[k] : N_NODES;   // zero row if past end
        v[k] = __ldg(&pay[idx * 2 + q]);
    }
#pragma unroll
    for (int k = 0; k < 16; k++) acc_h8(ac, v[k]);
}

__device__ __forceinline__ void gather_all(const uint4* __restrict__ pay,
                                           int node, int q, int len,
                                           float2* ac) {
    const int* base = g_csrp + node * CAP;
    gather16(pay, base, 0, len, q, ac);
    if (len > 16) {
        gather16(pay, base, 16, len, q, ac);
        if (len > 32) {
            gather16(pay, base, 32, len, q, ac);
            if (len > 48) gather16(pay, base, 48, len, q, ac);
        }
    }
}

// ---- K4: fused layer-1 agg + relu + layer-2 proj. 2 lanes/node ----
__global__ void __launch_bounds__(128, 6)
k_agg1p2(const float* __restrict__ w0,
         const float* __restrict__ w1,
         const float* __restrict__ b2) {
    __shared__ float sw0[HIDDEN][HIDDEN];   // [k][c], cols 10..15 = 0
    __shared__ float sw1[HIDDEN][HIDDEN];
    __shared__ float sb[HIDDEN];
    int t = threadIdx.x;
    for (int i = t; i < HIDDEN * HIDDEN; i += blockDim.x) {
        int k = i >> 4, c = i & 15;
        sw0[k][c] = (c < N_CLASSES) ? w0[k * N_CLASSES + c] : 0.0f;
        sw1[k][c] = (c < N_CLASSES) ? w1[k * N_CLASSES + c] : 0.0f;
    }
    if (t < HIDDEN) sb[t] = (t < N_CLASSES) ? b2[t] : 0.0f;
    __syncthreads();

    int gid  = blockIdx.x * blockDim.x + t;   // N_NODES*2 threads (guarded)
    int node = gid >> 1;
    int q    = gid & 1;
    if (node >= N_NODES) return;

    int len = g_cnt[node];
    float2 ac[4] = {{0.f,0.f},{0.f,0.f},{0.f,0.f},{0.f,0.f}};
    gather_all((const uint4*)g_xp1h, node, q, len, ac);

    float dn = g_dinv[node];
    const float4* xw = (const float4*)g_xw0;
    float4 f0 = xw[node * 4 + q * 2];
    float4 f1 = xw[node * 4 + q * 2 + 1];
    float h[8];
    h[0] = fmaxf(f0.x + dn * ac[0].x, 0.0f);
    h[1] = fmaxf(f0.y + dn * ac[0].y, 0.0f);
    h[2] = fmaxf(f0.z + dn * ac[1].x, 0.0f);
    h[3] = fmaxf(f0.w + dn * ac[1].y, 0.0f);
    h[4] = fmaxf(f1.x + dn * ac[2].x, 0.0f);
    h[5] = fmaxf(f1.y + dn * ac[2].y, 0.0f);
    h[6] = fmaxf(f1.z + dn * ac[3].x, 0.0f);
    h[7] = fmaxf(f1.w + dn * ac[3].y, 0.0f);

    // layer-2 projection: channels q*8..q*8+7 ; h[k] via width-2 shuffle
    float A0[8], A1[8];
    int cb = q * 8;
#pragma unroll
    for (int i = 0; i < 8; i++) { A0[i] = sb[cb + i]; A1[i] = 0.0f; }
#pragma unroll
    for (int k = 0; k < HIDDEN; k++) {
        float hk = __shfl_sync(0xffffffffu, h[k & 7], k >> 3, 2);
#pragma unroll
        for (int i = 0; i < 8; i++) {
            A0[i] = fmaf(hk, sw0[k][cb + i], A0[i]);
            A1[i] = fmaf(hk, sw1[k][cb + i], A1[i]);
        }
    }
    float4* hw = (float4*)g_hw;
    float4 o0, o1;
    o0.x = A0[0]; o0.y = A0[1]; o0.z = A0[2]; o0.w = A0[3];
    o1.x = A0[4]; o1.y = A0[5]; o1.z = A0[6]; o1.w = A0[7];
    hw[node * 4 + q * 2]     = o0;
    hw[node * 4 + q * 2 + 1] = o1;
    __half2 hp[4];
#pragma unroll
    for (int i = 0; i < 4; i++)
        hp[i] = __floats2half2_rn(dn * A1[2 * i], dn * A1[2 * i + 1]);
    ((uint4*)g_hph)[node * 2 + q] = *(uint4*)&hp[0];
}

// ---- K5: layer-2 aggregation + log_softmax; resets cnt for next replay ----
__global__ void __launch_bounds__(128, 6)
k_agg2(float* __restrict__ out) {
    int gid  = blockIdx.x * blockDim.x + threadIdx.x;
    int node = gid >> 1;
    int q    = gid & 1;
    if (node >= N_NODES) return;

    int len = g_cnt[node];
    if (q == 0) g_cnt[node] = 0;          // replay-idempotent
    float2 ac[4] = {{0.f,0.f},{0.f,0.f},{0.f,0.f},{0.f,0.f}};
    gather_all((const uint4*)g_hph, node, q, len, ac);

    float dn = g_dinv[node];
    const float4* hwv = (const float4*)g_hw;
    float4 f0 = hwv[node * 4 + q * 2];
    float4 f1 = hwv[node * 4 + q * 2 + 1];
    float L[8];
    L[0] = f0.x + dn * ac[0].x;
    L[1] = f0.y + dn * ac[0].y;
    L[2] = f0.z + dn * ac[1].x;
    L[3] = f0.w + dn * ac[1].y;
    L[4] = f1.x + dn * ac[2].x;
    L[5] = f1.y + dn * ac[2].y;
    L[6] = f1.z + dn * ac[3].x;
    L[7] = f1.w + dn * ac[3].y;

    // valid channels: lane 0 -> c0..7 (all), lane 1 -> c8,c9 (i<2)
    int nvalid = q ? 2 : 8;
    float m = -1e30f;
#pragma unroll
    for (int i = 0; i < 8; i++) if (i < nvalid) m = fmaxf(m, L[i]);
    m = fmaxf(m, __shfl_xor_sync(0xffffffffu, m, 1, 2));
    float s = 0.0f;
#pragma unroll
    for (int i = 0; i < 8; i++) if (i < nvalid) s += expf(L[i] - m);
    s += __shfl_xor_sync(0xffffffffu, s, 1, 2);
    float lse = m + logf(s);

    float* op = out + (size_t)node * N_CLASSES;
    if (q == 0) {
#pragma unroll
        for (int i = 0; i < 4; i++)
            ((float2*)op)[i] = make_float2(L[2 * i] - lse, L[2 * i + 1] - lse);
    } else {
        ((float2*)(op + 8))[0] = make_float2(L[0] - lse, L[1] - lse);
    }
}

// ---- host-side stream/event resources (created once at load; no device mem) ----
namespace {
struct ForkRes {
    cudaStream_t s2;
    cudaEvent_t evFork, evJoin;
    ForkRes() {
        cudaStreamCreateWithFlags(&s2, cudaStreamNonBlocking);
        cudaEventCreateWithFlags(&evFork, cudaEventDisableTiming);
        cudaEventCreateWithFlags(&evJoin, cudaEventDisableTiming);
    }
};
ForkRes g_fork;   // constructed before main
}

extern "C" void kernel_launch(void* const* d_in, const int* in_sizes, int n_in,
                              void* d_out, int out_size) {
    const float* x    = (const float*)d_in[0];
    const int*   ei   = (const int*)d_in[1];     // int32: JAX x64 disabled
    const float* w1_0 = (const float*)d_in[2];
    const float* w1_1 = (const float*)d_in[3];
    const float* b1   = (const float*)d_in[4];
    const float* w2_0 = (const float*)d_in[5];
    const float* w2_1 = (const float*)d_in[6];
    const float* b2   = (const float*)d_in[7];
    float* out = (float*)d_out;

    const int SB = (E4 + 255) / 256;               // 1563
    const int PB = (N_NODES + 255) / 256;          // 391
    const int GA = (N_NODES * 2 + 127) / 128;      // 1563

    // fork: proj (independent of scatter) runs on s2, scatter on stream 0
    cudaEventRecord(g_fork.evFork, 0);
    cudaStreamWaitEvent(g_fork.s2, g_fork.evFork, 0);
    k_projU<<<PB, 256, 0, g_fork.s2>>>(x, w1_0, w1_1, b1);
    cudaEventRecord(g_fork.evJoin, g_fork.s2);

    k_scatter1<<<SB, 256>>>(ei);

    // join: everything after needs both branches
    cudaStreamWaitEvent(0, g_fork.evJoin, 0);
    k_scale <<<PB, 256>>>();
    k_agg1p2<<<GA, 128>>>(w2_0, w2_1, b2);
    k_agg2  <<<GA, 128>>>(out);
}